// round 3
// baseline (speedup 1.0000x reference)
#include <cuda_runtime.h>
#include <cstdint>

#define MAXN 100000
#define MAXE 1600000
#define DIN  64

// ---------------- scratch (no cudaMalloc allowed) ----------------
__device__ float g_XE[(size_t)MAXN * 64];   // sum of e * X[src] per dst
__device__ float g_X1[(size_t)MAXN * 64];   // sum of X[src] per dst
__device__ float g_HA[(size_t)MAXN * 64];   // relu(layer1 out)
__device__ float g_HB[(size_t)MAXN * 64];   // relu(layer2 out)
__device__ int   g_counts[MAXN];
__device__ int   g_off[MAXN + 1];
__device__ int   g_cursor[MAXN];
__device__ int2  g_meta[MAXE];              // {src, bits(e)} grouped by dst

// packed f32x2 helpers (FFMA2 — only reachable via PTX)
#define FMA_F32X2(d, a, b) \
    asm("fma.rn.f32x2 %0, %1, %2, %0;" : "+l"(d) : "l"(a), "l"(b))
#define PACK2(out, f) \
    asm("mov.b64 %0, {%1, %1};" : "=l"(out) : "f"(f))
#define UNPACK2(lo, hi, in) \
    asm("mov.b64 {%0, %1}, %2;" : "=f"(lo), "=f"(hi) : "l"(in))

// =================================================================
// CSR build
// =================================================================
__global__ void hist_kernel(const int* __restrict__ ei, int* __restrict__ counts, int E)
{
    int e = blockIdx.x * blockDim.x + threadIdx.x;
    if (e < E) atomicAdd(&counts[__ldg(ei + E + e)], 1);
}

__global__ __launch_bounds__(1024) void scan_kernel(const int* __restrict__ counts,
                                                    int* __restrict__ off,
                                                    int* __restrict__ cursor, int N)
{
    __shared__ int ssum[1024];
    int tid = threadIdx.x;
    int chunk = (N + 1023) / 1024;
    int lo = tid * chunk;
    int hi = min(lo + chunk, N);
    int s = 0;
    for (int i = lo; i < hi; i++) s += counts[i];
    ssum[tid] = s;
    __syncthreads();
    for (int d = 1; d < 1024; d <<= 1) {
        int v = (tid >= d) ? ssum[tid - d] : 0;
        __syncthreads();
        ssum[tid] += v;
        __syncthreads();
    }
    int base = (tid == 0) ? 0 : ssum[tid - 1];
    for (int i = lo; i < hi; i++) {
        off[i] = base; cursor[i] = base;
        base += counts[i];
    }
    if (tid == 0) off[N] = ssum[1023];
}

__global__ void scatter_kernel(const int* __restrict__ ei, const float* __restrict__ ea,
                               int* __restrict__ cursor, int2* __restrict__ meta, int E)
{
    int e = blockIdx.x * blockDim.x + threadIdx.x;
    if (e >= E) return;
    int s = __ldg(ei + e);
    int d = __ldg(ei + E + e);
    int pos = atomicAdd(&cursor[d], 1);
    meta[pos] = make_int2(s, __float_as_int(__ldg(ea + e)));
}

// =================================================================
// Feature-space aggregation: XE[i] = sum e*X[s], X1[i] = sum X[s]
// one warp per node; lane owns 2 channels (float2); unroll-2 for MLP
// =================================================================
__global__ __launch_bounds__(256) void aggx_kernel(const int* __restrict__ off,
                                                   const int2* __restrict__ meta,
                                                   const float* __restrict__ X,
                                                   float* __restrict__ XE,
                                                   float* __restrict__ X1, int N)
{
    int w = (blockIdx.x * blockDim.x + threadIdx.x) >> 5;
    int lane = threadIdx.x & 31;
    if (w >= N) return;

    int beg = __ldg(off + w);
    int end = __ldg(off + w + 1);

    float2 aE = make_float2(0.f, 0.f);
    float2 a1 = make_float2(0.f, 0.f);

    int k = beg;
    for (; k + 2 <= end; k += 2) {
        int2 m0 = __ldg(meta + k);
        int2 m1 = __ldg(meta + k + 1);
        float2 v0 = *reinterpret_cast<const float2*>(X + (size_t)m0.x * 64 + lane * 2);
        float2 v1 = *reinterpret_cast<const float2*>(X + (size_t)m1.x * 64 + lane * 2);
        float e0 = __int_as_float(m0.y);
        float e1 = __int_as_float(m1.y);
        aE.x = fmaf(e0, v0.x, aE.x); aE.y = fmaf(e0, v0.y, aE.y);
        aE.x = fmaf(e1, v1.x, aE.x); aE.y = fmaf(e1, v1.y, aE.y);
        a1.x += v0.x + v1.x;         a1.y += v0.y + v1.y;
    }
    if (k < end) {
        int2 m0 = __ldg(meta + k);
        float2 v0 = *reinterpret_cast<const float2*>(X + (size_t)m0.x * 64 + lane * 2);
        float e0 = __int_as_float(m0.y);
        aE.x = fmaf(e0, v0.x, aE.x); aE.y = fmaf(e0, v0.y, aE.y);
        a1.x += v0.x;                a1.y += v0.y;
    }

    *reinterpret_cast<float2*>(XE + (size_t)w * 64 + lane * 2) = aE;
    *reinterpret_cast<float2*>(X1 + (size_t)w * 64 + lane * 2) = a1;
}

// =================================================================
// K=192 fused GEMM: H = relu?(XE@Wm + X1@Bm + X@Wr + b)
// 512 threads, 64-row tile, packed f32x2 accumulation.
// smem: 3 input tiles [64k x 68] + 3 weights [64x64] + bias
// =================================================================
#define TPAD 68
#define TILE_FLOATS (64 * TPAD)
#define G_SMEM_FLOATS (3 * TILE_FLOATS + 3 * 4096 + 64)
#define G_SMEM_BYTES  (G_SMEM_FLOATS * 4)

template<bool RELU>
__global__ __launch_bounds__(512) void gemm192(const float* __restrict__ XEp,
                                               const float* __restrict__ X1p,
                                               const float* __restrict__ Xp,
                                               const float* __restrict__ Wm,
                                               const float* __restrict__ Bm,
                                               const float* __restrict__ Wr,
                                               const float* __restrict__ bias,
                                               float* __restrict__ H, int N)
{
    extern __shared__ float sm[];
    float* sT = sm;                       // 3 tiles, [seg][k*TPAD + r]
    float* sW = sm + 3 * TILE_FLOATS;     // 3 weights, [seg][k*64 + c]
    float* sb = sW + 3 * 4096;

    const int tid = threadIdx.x;
    const int tx = tid & 63;              // output col
    const int ty = tid >> 6;              // 0..7, rows ty*8..ty*8+7
    const int row0 = blockIdx.x * 64;

    const float* srcs[3] = { XEp, X1p, Xp };

    // stage weights
    #pragma unroll
    for (int i = tid; i < 4096; i += 512) {
        sW[i]            = Wm[i];
        sW[4096 + i]     = Bm[i];
        sW[8192 + i]     = Wr[i];
    }
    if (tid < 64) sb[tid] = bias[tid];

    // stage 3 input tiles transposed (coalesced global reads)
    #pragma unroll
    for (int i = tid; i < 3 * 4096; i += 512) {
        int seg = i >> 12;
        int rem = i & 4095;
        int r = rem >> 6;
        int k = rem & 63;
        int row = row0 + r;
        float v = (row < N) ? srcs[seg][(size_t)row * 64 + k] : 0.f;
        sT[seg * TILE_FLOATS + k * TPAD + r] = v;
    }
    __syncthreads();

    unsigned long long acc0 = 0, acc1 = 0, acc2 = 0, acc3 = 0; // row pairs

    #pragma unroll
    for (int seg = 0; seg < 3; seg++) {
        const float* tile = sT + seg * TILE_FLOATS;
        const float* W = sW + seg * 4096;
        #pragma unroll 8
        for (int k = 0; k < 64; k++) {
            float w = W[k * 64 + tx];
            unsigned long long wp;
            PACK2(wp, w);
            const float* xr = tile + k * TPAD + ty * 8;
            ulonglong2 xa = *reinterpret_cast<const ulonglong2*>(xr);
            ulonglong2 xb = *reinterpret_cast<const ulonglong2*>(xr + 4);
            FMA_F32X2(acc0, xa.x, wp);
            FMA_F32X2(acc1, xa.y, wp);
            FMA_F32X2(acc2, xb.x, wp);
            FMA_F32X2(acc3, xb.y, wp);
        }
    }

    float b = sb[tx];
    float o[8];
    UNPACK2(o[0], o[1], acc0);
    UNPACK2(o[2], o[3], acc1);
    UNPACK2(o[4], o[5], acc2);
    UNPACK2(o[6], o[7], acc3);

    #pragma unroll
    for (int r = 0; r < 8; r++) {
        int row = row0 + ty * 8 + r;
        if (row < N) {
            float v = o[r] + b;
            if (RELU) v = fmaxf(v, 0.f);
            H[(size_t)row * 64 + tx] = v;
        }
    }
}

// =================================================================
// Layer 3 + log_softmax fused: out = logsm(XE@Wm3 + X1@Bm3 + HB@Wr3 + b3)
// one thread per node row
// =================================================================
__global__ __launch_bounds__(256) void gemm3_ls(const float* __restrict__ XEp,
                                                const float* __restrict__ X1p,
                                                const float* __restrict__ Xp,
                                                const float* __restrict__ Wm,
                                                const float* __restrict__ Bm,
                                                const float* __restrict__ Wr,
                                                const float* __restrict__ b,
                                                float* __restrict__ OUT, int N)
{
    __shared__ float sw[768];   // [0:256) Wm, [256:512) Bm, [512:768) Wr  layout k*4+c
    int tid = threadIdx.x;
    if (tid < 256) { sw[tid] = Wm[tid]; sw[256 + tid] = Bm[tid]; sw[512 + tid] = Wr[tid]; }
    __syncthreads();

    int row = blockIdx.x * blockDim.x + tid;
    if (row >= N) return;

    float acc[4] = {0.f, 0.f, 0.f, 0.f};
    const float4* xe = reinterpret_cast<const float4*>(XEp + (size_t)row * 64);
    const float4* x1 = reinterpret_cast<const float4*>(X1p + (size_t)row * 64);
    const float4* xp = reinterpret_cast<const float4*>(Xp  + (size_t)row * 64);

    #pragma unroll 4
    for (int k4 = 0; k4 < 16; k4++) {
        float4 ve = __ldg(xe + k4);
        float4 v1 = __ldg(x1 + k4);
        float4 vx = __ldg(xp + k4);
        float es[4] = {ve.x, ve.y, ve.z, ve.w};
        float os[4] = {v1.x, v1.y, v1.z, v1.w};
        float xs[4] = {vx.x, vx.y, vx.z, vx.w};
        #pragma unroll
        for (int j = 0; j < 4; j++) {
            int k = k4 * 4 + j;
            #pragma unroll
            for (int c = 0; c < 4; c++) {
                acc[c] = fmaf(es[j], sw[k * 4 + c], acc[c]);
                acc[c] = fmaf(os[j], sw[256 + k * 4 + c], acc[c]);
                acc[c] = fmaf(xs[j], sw[512 + k * 4 + c], acc[c]);
            }
        }
    }
    #pragma unroll
    for (int c = 0; c < 4; c++) acc[c] += __ldg(b + c);

    float m = fmaxf(fmaxf(acc[0], acc[1]), fmaxf(acc[2], acc[3]));
    float s = __expf(acc[0] - m) + __expf(acc[1] - m) +
              __expf(acc[2] - m) + __expf(acc[3] - m);
    float lse = m + __logf(s);

    float4 o;
    o.x = acc[0] - lse; o.y = acc[1] - lse; o.z = acc[2] - lse; o.w = acc[3] - lse;
    *reinterpret_cast<float4*>(OUT + (size_t)row * 4) = o;
}

// =================================================================
extern "C" void kernel_launch(void* const* d_in, const int* in_sizes, int n_in,
                              void* d_out, int out_size)
{
    const float* x   = (const float*)d_in[0];
    const int*   ei  = (const int*)  d_in[1];
    const float* ea  = (const float*)d_in[2];
    const float* We1 = (const float*)d_in[3];
    const float* be1 = (const float*)d_in[4];
    const float* Wr1 = (const float*)d_in[5];
    const float* b1  = (const float*)d_in[6];
    const float* We2 = (const float*)d_in[7];
    const float* be2 = (const float*)d_in[8];
    const float* Wr2 = (const float*)d_in[9];
    const float* b2  = (const float*)d_in[10];
    const float* We3 = (const float*)d_in[11];
    const float* be3 = (const float*)d_in[12];
    const float* Wr3 = (const float*)d_in[13];
    const float* b3  = (const float*)d_in[14];

    const int N = in_sizes[0] / DIN;
    const int E = in_sizes[2];

    float *XE, *X1, *HA, *HB;
    int *counts, *off, *cursor;
    int2 *meta;
    cudaGetSymbolAddress((void**)&XE, g_XE);
    cudaGetSymbolAddress((void**)&X1, g_X1);
    cudaGetSymbolAddress((void**)&HA, g_HA);
    cudaGetSymbolAddress((void**)&HB, g_HB);
    cudaGetSymbolAddress((void**)&counts, g_counts);
    cudaGetSymbolAddress((void**)&off, g_off);
    cudaGetSymbolAddress((void**)&cursor, g_cursor);
    cudaGetSymbolAddress((void**)&meta, g_meta);
    float* OUT = (float*)d_out;

    cudaFuncSetAttribute(gemm192<false>, cudaFuncAttributeMaxDynamicSharedMemorySize, G_SMEM_BYTES);
    cudaFuncSetAttribute(gemm192<true>,  cudaFuncAttributeMaxDynamicSharedMemorySize, G_SMEM_BYTES);

    const int edgeGrid = (E + 255) / 256;
    const int rowGrid  = (N + 255) / 256;
    const int aggGrid  = (N * 32 + 255) / 256;
    const int gemmGrid = (N + 63) / 64;

    // ---- CSR build (reused by all 3 layers) ----
    cudaMemsetAsync(counts, 0, (size_t)N * sizeof(int));
    hist_kernel<<<edgeGrid, 256>>>(ei, counts, E);
    scan_kernel<<<1, 1024>>>(counts, off, cursor, N);
    scatter_kernel<<<edgeGrid, 256>>>(ei, ea, cursor, meta, E);

    // ---- layer 1: agg on x, then fused GEMM -> relu'd HA ----
    aggx_kernel<<<aggGrid, 256>>>(off, meta, x, XE, X1, N);
    gemm192<true><<<gemmGrid, 512, G_SMEM_BYTES>>>(XE, X1, x, We1, be1, Wr1, b1, HA, N);

    // ---- layer 2: agg on HA, fused GEMM -> relu'd HB ----
    aggx_kernel<<<aggGrid, 256>>>(off, meta, HA, XE, X1, N);
    gemm192<true><<<gemmGrid, 512, G_SMEM_BYTES>>>(XE, X1, HA, We2, be2, Wr2, b2, HB, N);

    // ---- layer 3: agg on HB, tiny GEMM + log_softmax fused ----
    aggx_kernel<<<aggGrid, 256>>>(off, meta, HB, XE, X1, N);
    gemm3_ls<<<rowGrid, 256>>>(XE, X1, HB, We3, be3, Wr3, b3, OUT, N);
}

// round 4
// speedup vs baseline: 1.0575x; 1.0575x over previous
#include <cuda_runtime.h>
#include <cstdint>

#define MAXN 100000
#define MAXE 1600000
#define DIN  64

// ---------------- scratch (no cudaMalloc allowed) ----------------
__device__ float g_XE[(size_t)MAXN * 64];   // sum of e * X[src] per dst
__device__ float g_X1[(size_t)MAXN * 64];   // sum of X[src] per dst
__device__ float g_HA[(size_t)MAXN * 64];   // relu(layer1 out)
__device__ float g_HB[(size_t)MAXN * 64];   // relu(layer2 out)
__device__ int   g_counts[MAXN];
__device__ int   g_off[MAXN + 1];
__device__ int   g_cursor[MAXN];
__device__ int2  g_meta[MAXE];              // {src, bits(e)} grouped by dst

// =================================================================
// CSR build
// =================================================================
__global__ void hist_kernel(const int* __restrict__ ei, int* __restrict__ counts, int E)
{
    int e = blockIdx.x * blockDim.x + threadIdx.x;
    if (e < E) atomicAdd(&counts[__ldg(ei + E + e)], 1);
}

__global__ __launch_bounds__(1024) void scan_kernel(const int* __restrict__ counts,
                                                    int* __restrict__ off,
                                                    int* __restrict__ cursor, int N)
{
    __shared__ int ssum[1024];
    int tid = threadIdx.x;
    int chunk = (N + 1023) / 1024;
    int lo = tid * chunk;
    int hi = min(lo + chunk, N);
    int s = 0;
    for (int i = lo; i < hi; i++) s += counts[i];
    ssum[tid] = s;
    __syncthreads();
    for (int d = 1; d < 1024; d <<= 1) {
        int v = (tid >= d) ? ssum[tid - d] : 0;
        __syncthreads();
        ssum[tid] += v;
        __syncthreads();
    }
    int base = (tid == 0) ? 0 : ssum[tid - 1];
    for (int i = lo; i < hi; i++) {
        off[i] = base; cursor[i] = base;
        base += counts[i];
    }
    if (tid == 0) off[N] = ssum[1023];
}

__global__ void scatter_kernel(const int* __restrict__ ei, const float* __restrict__ ea,
                               int* __restrict__ cursor, int2* __restrict__ meta, int E)
{
    int e = blockIdx.x * blockDim.x + threadIdx.x;
    if (e >= E) return;
    int s = __ldg(ei + e);
    int d = __ldg(ei + E + e);
    int pos = atomicAdd(&cursor[d], 1);
    meta[pos] = make_int2(s, __float_as_int(__ldg(ea + e)));
}

// =================================================================
// Feature-space aggregation: XE[i] = sum e*X[s], X1[i] = sum X[s]
// HALF-warp per node; lane owns 4 channels (float4); unroll-2 for MLP
// =================================================================
__global__ __launch_bounds__(256) void aggx_kernel(const int* __restrict__ off,
                                                   const int2* __restrict__ meta,
                                                   const float* __restrict__ X,
                                                   float* __restrict__ XE,
                                                   float* __restrict__ X1, int N)
{
    int t = blockIdx.x * blockDim.x + threadIdx.x;
    int g = t >> 4;            // node
    int lane = t & 15;         // 4-channel group
    if (g >= N) return;

    int beg = __ldg(off + g);
    int end = __ldg(off + g + 1);

    float4 aE = make_float4(0.f, 0.f, 0.f, 0.f);
    float4 a1 = make_float4(0.f, 0.f, 0.f, 0.f);

    int k = beg;
    for (; k + 2 <= end; k += 2) {
        int2 m0 = __ldg(meta + k);
        int2 m1 = __ldg(meta + k + 1);
        float4 v0 = *reinterpret_cast<const float4*>(X + (size_t)m0.x * 64 + lane * 4);
        float4 v1 = *reinterpret_cast<const float4*>(X + (size_t)m1.x * 64 + lane * 4);
        float e0 = __int_as_float(m0.y);
        float e1 = __int_as_float(m1.y);
        aE.x = fmaf(e0, v0.x, aE.x); aE.y = fmaf(e0, v0.y, aE.y);
        aE.z = fmaf(e0, v0.z, aE.z); aE.w = fmaf(e0, v0.w, aE.w);
        aE.x = fmaf(e1, v1.x, aE.x); aE.y = fmaf(e1, v1.y, aE.y);
        aE.z = fmaf(e1, v1.z, aE.z); aE.w = fmaf(e1, v1.w, aE.w);
        a1.x += v0.x + v1.x; a1.y += v0.y + v1.y;
        a1.z += v0.z + v1.z; a1.w += v0.w + v1.w;
    }
    if (k < end) {
        int2 m0 = __ldg(meta + k);
        float4 v0 = *reinterpret_cast<const float4*>(X + (size_t)m0.x * 64 + lane * 4);
        float e0 = __int_as_float(m0.y);
        aE.x = fmaf(e0, v0.x, aE.x); aE.y = fmaf(e0, v0.y, aE.y);
        aE.z = fmaf(e0, v0.z, aE.z); aE.w = fmaf(e0, v0.w, aE.w);
        a1.x += v0.x; a1.y += v0.y; a1.z += v0.z; a1.w += v0.w;
    }

    *reinterpret_cast<float4*>(XE + (size_t)g * 64 + lane * 4) = aE;
    *reinterpret_cast<float4*>(X1 + (size_t)g * 64 + lane * 4) = a1;
}

// =================================================================
// K=192 fused GEMM: H = relu?(XE@Wm + X1@Bm + X@Wr + b)
// 256 threads, 64-row tile, 2 cols x 8 rows per thread, plain FFMA.
// smem: 3 transposed tiles [64k x 68pad] + 3 weights [64x64] + bias
// =================================================================
#define TPAD 68
#define TILE_FLOATS (64 * TPAD)
#define G_SMEM_FLOATS (3 * TILE_FLOATS + 3 * 4096 + 64)
#define G_SMEM_BYTES  (G_SMEM_FLOATS * 4)

template<bool RELU>
__global__ __launch_bounds__(256) void gemm192(const float* __restrict__ XEp,
                                               const float* __restrict__ X1p,
                                               const float* __restrict__ Xp,
                                               const float* __restrict__ Wm,
                                               const float* __restrict__ Bm,
                                               const float* __restrict__ Wr,
                                               const float* __restrict__ bias,
                                               float* __restrict__ H, int N)
{
    extern __shared__ float sm[];
    float* sT = sm;                       // 3 tiles, [seg][k*TPAD + r]
    float* sW = sm + 3 * TILE_FLOATS;     // 3 weights, [seg][k*64 + c]
    float* sb = sW + 3 * 4096;

    const int tid = threadIdx.x;
    const int txc = (tid & 31) * 2;       // output col pair
    const int ty  = tid >> 5;             // 0..7, rows ty*8..+7
    const int row0 = blockIdx.x * 64;

    // stage weights (3 explicit loops; no dynamic local arrays)
    #pragma unroll
    for (int i = tid; i < 4096; i += 256) {
        sW[i]        = Wm[i];
        sW[4096 + i] = Bm[i];
        sW[8192 + i] = Wr[i];
    }
    if (tid < 64) sb[tid] = bias[tid];

    // stage 3 input tiles transposed (coalesced global reads)
    #pragma unroll
    for (int i = tid; i < 4096; i += 256) {
        int r = i >> 6;
        int k = i & 63;
        int row = row0 + r;
        bool ok = row < N;
        float v0 = ok ? XEp[(size_t)row * 64 + k] : 0.f;
        float v1 = ok ? X1p[(size_t)row * 64 + k] : 0.f;
        float v2 = ok ? Xp [(size_t)row * 64 + k] : 0.f;
        sT[                  k * TPAD + r] = v0;
        sT[    TILE_FLOATS + k * TPAD + r] = v1;
        sT[2 * TILE_FLOATS + k * TPAD + r] = v2;
    }
    __syncthreads();

    float2 acc[8];
    #pragma unroll
    for (int r = 0; r < 8; r++) acc[r] = make_float2(0.f, 0.f);

    #pragma unroll
    for (int seg = 0; seg < 3; seg++) {
        const float* tile = sT + seg * TILE_FLOATS;
        const float* W    = sW + seg * 4096;
        #pragma unroll 8
        for (int k = 0; k < 64; k++) {
            float2 w = *reinterpret_cast<const float2*>(&W[k * 64 + txc]);
            const float* xr = tile + k * TPAD + ty * 8;
            float4 xa = *reinterpret_cast<const float4*>(xr);
            float4 xb = *reinterpret_cast<const float4*>(xr + 4);
            float xs[8] = {xa.x, xa.y, xa.z, xa.w, xb.x, xb.y, xb.z, xb.w};
            #pragma unroll
            for (int r = 0; r < 8; r++) {
                acc[r].x = fmaf(xs[r], w.x, acc[r].x);
                acc[r].y = fmaf(xs[r], w.y, acc[r].y);
            }
        }
    }

    float2 b2 = *reinterpret_cast<const float2*>(&sb[txc]);
    #pragma unroll
    for (int r = 0; r < 8; r++) {
        int row = row0 + ty * 8 + r;
        if (row < N) {
            float2 v;
            v.x = acc[r].x + b2.x;
            v.y = acc[r].y + b2.y;
            if (RELU) { v.x = fmaxf(v.x, 0.f); v.y = fmaxf(v.y, 0.f); }
            *reinterpret_cast<float2*>(H + (size_t)row * 64 + txc) = v;
        }
    }
}

// =================================================================
// Layer 3 + log_softmax fused: out = logsm(XE@Wm3 + X1@Bm3 + HB@Wr3 + b3)
// =================================================================
__global__ __launch_bounds__(256) void gemm3_ls(const float* __restrict__ XEp,
                                                const float* __restrict__ X1p,
                                                const float* __restrict__ Xp,
                                                const float* __restrict__ Wm,
                                                const float* __restrict__ Bm,
                                                const float* __restrict__ Wr,
                                                const float* __restrict__ b,
                                                float* __restrict__ OUT, int N)
{
    __shared__ float sw[768];   // [0:256) Wm, [256:512) Bm, [512:768) Wr  layout k*4+c
    int tid = threadIdx.x;
    if (tid < 256) { sw[tid] = Wm[tid]; sw[256 + tid] = Bm[tid]; sw[512 + tid] = Wr[tid]; }
    __syncthreads();

    int row = blockIdx.x * blockDim.x + tid;
    if (row >= N) return;

    float acc[4] = {0.f, 0.f, 0.f, 0.f};
    const float4* xe = reinterpret_cast<const float4*>(XEp + (size_t)row * 64);
    const float4* x1 = reinterpret_cast<const float4*>(X1p + (size_t)row * 64);
    const float4* xp = reinterpret_cast<const float4*>(Xp  + (size_t)row * 64);

    #pragma unroll 4
    for (int k4 = 0; k4 < 16; k4++) {
        float4 ve = __ldg(xe + k4);
        float4 v1 = __ldg(x1 + k4);
        float4 vx = __ldg(xp + k4);
        float es[4] = {ve.x, ve.y, ve.z, ve.w};
        float os[4] = {v1.x, v1.y, v1.z, v1.w};
        float xs[4] = {vx.x, vx.y, vx.z, vx.w};
        #pragma unroll
        for (int j = 0; j < 4; j++) {
            int k = k4 * 4 + j;
            #pragma unroll
            for (int c = 0; c < 4; c++) {
                acc[c] = fmaf(es[j], sw[k * 4 + c], acc[c]);
                acc[c] = fmaf(os[j], sw[256 + k * 4 + c], acc[c]);
                acc[c] = fmaf(xs[j], sw[512 + k * 4 + c], acc[c]);
            }
        }
    }
    #pragma unroll
    for (int c = 0; c < 4; c++) acc[c] += __ldg(b + c);

    float m = fmaxf(fmaxf(acc[0], acc[1]), fmaxf(acc[2], acc[3]));
    float s = __expf(acc[0] - m) + __expf(acc[1] - m) +
              __expf(acc[2] - m) + __expf(acc[3] - m);
    float lse = m + __logf(s);

    float4 o;
    o.x = acc[0] - lse; o.y = acc[1] - lse; o.z = acc[2] - lse; o.w = acc[3] - lse;
    *reinterpret_cast<float4*>(OUT + (size_t)row * 4) = o;
}

// =================================================================
extern "C" void kernel_launch(void* const* d_in, const int* in_sizes, int n_in,
                              void* d_out, int out_size)
{
    const float* x   = (const float*)d_in[0];
    const int*   ei  = (const int*)  d_in[1];
    const float* ea  = (const float*)d_in[2];
    const float* We1 = (const float*)d_in[3];
    const float* be1 = (const float*)d_in[4];
    const float* Wr1 = (const float*)d_in[5];
    const float* b1  = (const float*)d_in[6];
    const float* We2 = (const float*)d_in[7];
    const float* be2 = (const float*)d_in[8];
    const float* Wr2 = (const float*)d_in[9];
    const float* b2  = (const float*)d_in[10];
    const float* We3 = (const float*)d_in[11];
    const float* be3 = (const float*)d_in[12];
    const float* Wr3 = (const float*)d_in[13];
    const float* b3  = (const float*)d_in[14];

    const int N = in_sizes[0] / DIN;
    const int E = in_sizes[2];

    float *XE, *X1, *HA, *HB;
    int *counts, *off, *cursor;
    int2 *meta;
    cudaGetSymbolAddress((void**)&XE, g_XE);
    cudaGetSymbolAddress((void**)&X1, g_X1);
    cudaGetSymbolAddress((void**)&HA, g_HA);
    cudaGetSymbolAddress((void**)&HB, g_HB);
    cudaGetSymbolAddress((void**)&counts, g_counts);
    cudaGetSymbolAddress((void**)&off, g_off);
    cudaGetSymbolAddress((void**)&cursor, g_cursor);
    cudaGetSymbolAddress((void**)&meta, g_meta);
    float* OUT = (float*)d_out;

    cudaFuncSetAttribute(gemm192<false>, cudaFuncAttributeMaxDynamicSharedMemorySize, G_SMEM_BYTES);
    cudaFuncSetAttribute(gemm192<true>,  cudaFuncAttributeMaxDynamicSharedMemorySize, G_SMEM_BYTES);

    const int edgeGrid = (E + 255) / 256;
    const int rowGrid  = (N + 255) / 256;
    const int aggGrid  = (N * 16 + 255) / 256;
    const int gemmGrid = (N + 63) / 64;

    // ---- CSR build (reused by all 3 layers) ----
    cudaMemsetAsync(counts, 0, (size_t)N * sizeof(int));
    hist_kernel<<<edgeGrid, 256>>>(ei, counts, E);
    scan_kernel<<<1, 1024>>>(counts, off, cursor, N);
    scatter_kernel<<<edgeGrid, 256>>>(ei, ea, cursor, meta, E);

    // ---- layer 1 ----
    aggx_kernel<<<aggGrid, 256>>>(off, meta, x, XE, X1, N);
    gemm192<true><<<gemmGrid, 256, G_SMEM_BYTES>>>(XE, X1, x, We1, be1, Wr1, b1, HA, N);

    // ---- layer 2 ----
    aggx_kernel<<<aggGrid, 256>>>(off, meta, HA, XE, X1, N);
    gemm192<true><<<gemmGrid, 256, G_SMEM_BYTES>>>(XE, X1, HA, We2, be2, Wr2, b2, HB, N);

    // ---- layer 3 ----
    aggx_kernel<<<aggGrid, 256>>>(off, meta, HB, XE, X1, N);
    gemm3_ls<<<rowGrid, 256>>>(XE, X1, HB, We3, be3, Wr3, b3, OUT, N);
}